// round 10
// baseline (speedup 1.0000x reference)
#include <cuda_runtime.h>
#include <cstdint>

namespace {

constexpr int Bsz = 512, Msl = 32, DIN = 1024, DH = 4096, DOUT = 1024;
constexpr int BM = 128, BN = 128, BK = 32;
constexpr int A_TILE = BM * BK * 4;       // 16 KB
constexpr int B_TILE = BN * BK * 4;       // 16 KB
constexpr int STAGE  = A_TILE + B_TILE;   // 32 KB
constexpr int SMEM_DYN = 2 * STAGE;       // 64 KB ping-pong -> 2 CTAs/SM

// Intermediate h: [m][b][dh], stored tf32-rounded by layer-1 epilogue.
__device__ float g_h[(size_t)Bsz * Msl * DH];
// x pre-rounded to tf32 bits (pre-pass kernel).
__device__ float g_x_tf[(size_t)Bsz * Msl * DIN];

__device__ __forceinline__ uint32_t f2tf(float f) {
    uint32_t u; asm("cvt.rna.tf32.f32 %0, %1;" : "=r"(u) : "f"(f)); return u;
}
__device__ __forceinline__ uint32_t smem_u32(const void* p) {
    uint32_t a;
    asm("{ .reg .u64 t; cvta.to.shared.u64 t, %1; cvt.u32.u64 %0, t; }" : "=r"(a) : "l"(p));
    return a;
}
__device__ __forceinline__ void cp16(uint32_t dst, const void* src) {
    asm volatile("cp.async.cg.shared.global [%0], [%1], 16;" :: "r"(dst), "l"(src));
}
#define CP_COMMIT() asm volatile("cp.async.commit_group;" ::: "memory")
#define CP_WAIT0()  asm volatile("cp.async.wait_group 0;" ::: "memory")

__device__ __forceinline__ void ldsm4(uint32_t r[4], uint32_t addr) {
    asm volatile("ldmatrix.sync.aligned.m8n8.x4.shared.b16 {%0,%1,%2,%3}, [%4];"
                 : "=r"(r[0]), "=r"(r[1]), "=r"(r[2]), "=r"(r[3]) : "r"(addr));
}
__device__ __forceinline__ void mma_tf32(float acc[4], const uint32_t a[4],
                                         uint32_t b0, uint32_t b1) {
    asm volatile(
        "mma.sync.aligned.m16n8k8.row.col.f32.tf32.tf32.f32 "
        "{%0,%1,%2,%3}, {%4,%5,%6,%7}, {%8,%9}, {%0,%1,%2,%3};\n"
        : "+f"(acc[0]), "+f"(acc[1]), "+f"(acc[2]), "+f"(acc[3])
        : "r"(a[0]), "r"(a[1]), "r"(a[2]), "r"(a[3]), "r"(b0), "r"(b1));
}

// Pre-pass: round x to tf32 bits (vectorized).
__global__ void __launch_bounds__(256)
cvt_tf32(const float4* __restrict__ in, float4* __restrict__ out, int n4) {
    int i = blockIdx.x * blockDim.x + threadIdx.x;
    if (i < n4) {
        float4 v = in[i];
        float4 o;
        o.x = __uint_as_float(f2tf(v.x));
        o.y = __uint_as_float(f2tf(v.y));
        o.z = __uint_as_float(f2tf(v.z));
        o.w = __uint_as_float(f2tf(v.w));
        out[i] = o;
    }
}

// C[BM,BN] tile of A[*,K] x W[K,*] (+bias, optional ReLU), batched over blockIdx.z.
// Ping-pong smem, loop unrolled x2 (buf compile-time), last iteration peeled,
// all addresses hoisted to incremented pointers / reg+imm.
template<bool RELU, bool ROUND_OUT>
__global__ void __launch_bounds__(256, 2)
gemm_tf32(const float* __restrict__ Ag, const float* __restrict__ Wg,
          const float* __restrict__ biasg, float* __restrict__ Cg,
          int K,
          long aBatch, int lda, long wBatch, int ldw,
          long biasBatch, long cBatch, int ldc)
{
    extern __shared__ char sm[];
    const uint32_t sb = smem_u32(sm);

    const int tid  = threadIdx.x;
    const int lane = tid & 31, warp = tid >> 5;
    const int g = lane >> 2, tg = lane & 3;
    const int wm = warp & 3, wn = warp >> 2;          // 4 (m) x 2 (n) warps

    const int m0 = blockIdx.y * BM;
    const int n0 = blockIdx.x * BN;
    const float* A    = Ag    + (size_t)blockIdx.z * aBatch;
    const float* W    = Wg    + (size_t)blockIdx.z * wBatch;
    const float* bias = biasg + (size_t)blockIdx.z * biasBatch;
    float*       C    = Cg    + (size_t)blockIdx.z * cBatch;

    // ---- hoisted per-thread constants ----
    const int a_kg = tid & 7;
    const int a_r0 = tid >> 3;
    const int b_n  = (tid & 31) * 4;
    const int b_k0 = (tid >> 5) * 4;
    const int rot  = (lane >> 1) & 3;
    const int lrow = lane & 15;
    const int lkh  = (lane >> 4) << 4;

    // A cp.async: 4 row pointers, advanced += BK per stage; dst = imm offsets
    const size_t a_rowstep = 32 * (size_t)lda;
    const float* a_src0 = A + (size_t)(m0 + a_r0) * lda + a_kg * 4;
    const float* a_src1 = a_src0 + a_rowstep;
    const float* a_src2 = a_src1 + a_rowstep;
    const float* a_src3 = a_src2 + a_rowstep;
    const uint32_t a_dst0 = sb + (uint32_t)(a_r0 * 128 + ((a_kg * 16) ^ ((a_r0 & 7) << 4)));

    // B LDG: base pointer advanced += BK*ldw per stage
    const float* w_src = W + (size_t)b_k0 * ldw + n0 + b_n;
    const size_t w_step = (size_t)BK * ldw;
    // B STS: 4 fixed smem offsets (store order permuted by rot)
    uint32_t boff[4];
    #pragma unroll
    for (int p = 0; p < 4; ++p) {
        const int row = b_n + p;
        boff[p] = (uint32_t)(row * 128 + ((b_k0 * 4) ^ ((row & 7) << 4)));
    }

    // LDSM bases: A/B share the xor term (row&7 == lrow&7 for all frag rows)
    const uint32_t cxor = (uint32_t)((lrow & 7) << 4);
    uint32_t xoff[4];
    #pragma unroll
    for (int ks = 0; ks < 4; ++ks) xoff[ks] = (uint32_t)((ks * 32 + lkh) ^ cxor);
    const uint32_t warpA = sb + (uint32_t)((wm * 32 + lrow) * 128);
    const uint32_t warpB = sb + A_TILE + (uint32_t)((wn * 64 + lrow) * 128);

    float acc[2][8][4];
    #pragma unroll
    for (int i = 0; i < 2; i++)
        #pragma unroll
        for (int j = 0; j < 8; j++)
            #pragma unroll
            for (int q = 0; q < 4; q++) acc[i][j][q] = 0.f;

    float4 rb[4];

    auto cpA = [&](uint32_t dstbuf) {   // dstbuf: 0 or STAGE (literal)
        cp16(a_dst0 + dstbuf,          a_src0);
        cp16(a_dst0 + dstbuf + 4096,   a_src1);
        cp16(a_dst0 + dstbuf + 8192,   a_src2);
        cp16(a_dst0 + dstbuf + 12288,  a_src3);
        a_src0 += BK; a_src1 += BK; a_src2 += BK; a_src3 += BK;
    };
    auto ldgB = [&]() {
        rb[0] = *(const float4*)(w_src);
        rb[1] = *(const float4*)(w_src + (size_t)ldw);
        rb[2] = *(const float4*)(w_src + 2 * (size_t)ldw);
        rb[3] = *(const float4*)(w_src + 3 * (size_t)ldw);
        w_src += w_step;
    };
    auto stsB = [&](uint32_t dstbuf) {
        uint4 c[4];
        c[0].x = f2tf(rb[0].x); c[0].y = f2tf(rb[1].x); c[0].z = f2tf(rb[2].x); c[0].w = f2tf(rb[3].x);
        c[1].x = f2tf(rb[0].y); c[1].y = f2tf(rb[1].y); c[1].z = f2tf(rb[2].y); c[1].w = f2tf(rb[3].y);
        c[2].x = f2tf(rb[0].z); c[2].y = f2tf(rb[1].z); c[2].z = f2tf(rb[2].z); c[2].w = f2tf(rb[3].z);
        c[3].x = f2tf(rb[0].w); c[3].y = f2tf(rb[1].w); c[3].z = f2tf(rb[2].w); c[3].w = f2tf(rb[3].w);
        #pragma unroll
        for (int j = 0; j < 4; ++j) {
            const int p = (j + rot) & 3;
            *(uint4*)(sm + dstbuf + A_TILE + boff[p]) = c[p];
        }
    };

    auto compute = [&](uint32_t buf) {  // buf: 0 or STAGE (literal)
        #pragma unroll
        for (int ks = 0; ks < 4; ++ks) {
            const uint32_t tA = warpA + buf + xoff[ks];
            const uint32_t tB = warpB + buf + xoff[ks];
            uint32_t af[2][4];
            ldsm4(af[0], tA);
            ldsm4(af[1], tA + 2048);
            uint32_t bf[4][4];
            ldsm4(bf[0], tB);
            ldsm4(bf[1], tB + 2048);
            ldsm4(bf[2], tB + 4096);
            ldsm4(bf[3], tB + 6144);
            #pragma unroll
            for (int mt = 0; mt < 2; ++mt)
                #pragma unroll
                for (int nt = 0; nt < 8; ++nt)
                    mma_tf32(acc[mt][nt], af[mt],
                             bf[nt >> 1][nt & 1], bf[nt >> 1][(nt & 1) + 2]);
        }
    };

    const int S = K / BK;               // 32 or 128, always even
    const int S2 = S / 2;

    // Preamble: stage 0 -> buf0; rb <- stage 1
    cpA(0); CP_COMMIT();
    ldgB();
    stsB(0);
    ldgB();
    CP_WAIT0();
    __syncthreads();

    // Hot loop: two stages per iteration, zero conditionals (last iter peeled)
    #pragma unroll 1
    for (int s2 = 0; s2 < S2 - 1; ++s2) {
        // stage s (buf0); rb holds s+1
        cpA(STAGE); CP_COMMIT();
        compute(0);
        stsB(STAGE);
        ldgB();                         // rb <- s+2
        CP_WAIT0();
        __syncthreads();
        // stage s+1 (buf1); rb holds s+2
        cpA(0); CP_COMMIT();
        compute(STAGE);
        stsB(0);
        ldgB();                         // rb <- s+3
        CP_WAIT0();
        __syncthreads();
    }
    // Peeled tail: stages S-2, S-1 (rb holds S-1)
    cpA(STAGE); CP_COMMIT();
    compute(0);
    stsB(STAGE);
    CP_WAIT0();
    __syncthreads();
    compute(STAGE);

    // epilogue: +bias, optional relu, optional tf32 rounding, float2 stores
    #pragma unroll
    for (int mt = 0; mt < 2; ++mt) {
        const int r = m0 + wm * 32 + mt * 16 + g;
        #pragma unroll
        for (int nt = 0; nt < 8; ++nt) {
            const int c = n0 + wn * 64 + nt * 8 + tg * 2;
            const float b0v = bias[c], b1v = bias[c + 1];
            float v0 = acc[mt][nt][0] + b0v;
            float v1 = acc[mt][nt][1] + b1v;
            float v2 = acc[mt][nt][2] + b0v;
            float v3 = acc[mt][nt][3] + b1v;
            if (RELU) {
                v0 = fmaxf(v0, 0.f); v1 = fmaxf(v1, 0.f);
                v2 = fmaxf(v2, 0.f); v3 = fmaxf(v3, 0.f);
            }
            if (ROUND_OUT) {
                v0 = __uint_as_float(f2tf(v0));
                v1 = __uint_as_float(f2tf(v1));
                v2 = __uint_as_float(f2tf(v2));
                v3 = __uint_as_float(f2tf(v3));
            }
            float2 p0; p0.x = v0; p0.y = v1;
            float2 p1; p1.x = v2; p1.y = v3;
            *(float2*)(C + (size_t)r * ldc + c)       = p0;
            *(float2*)(C + (size_t)(r + 8) * ldc + c) = p1;
        }
    }
}

} // anonymous namespace

extern "C" void kernel_launch(void* const* d_in, const int* in_sizes, int n_in,
                              void* d_out, int out_size) {
    (void)in_sizes; (void)n_in; (void)out_size;
    const float* x  = (const float*)d_in[0];  // [B, M, DIN]
    const float* W1 = (const float*)d_in[1];  // [M, DIN, DH]
    const float* b1 = (const float*)d_in[2];  // [M, DH]
    const float* W2 = (const float*)d_in[3];  // [M, DH, DOUT]
    const float* b2 = (const float*)d_in[4];  // [M, DOUT]
    float* out = (float*)d_out;               // [B, M, DOUT]

    float* h = nullptr;
    cudaGetSymbolAddress((void**)&h, g_h);
    float* x_tf = nullptr;
    cudaGetSymbolAddress((void**)&x_tf, g_x_tf);

    cudaFuncSetAttribute(gemm_tf32<true, true>,   cudaFuncAttributeMaxDynamicSharedMemorySize, SMEM_DYN);
    cudaFuncSetAttribute(gemm_tf32<false, false>, cudaFuncAttributeMaxDynamicSharedMemorySize, SMEM_DYN);

    // Pre-pass: x -> tf32 bits (~19 us)
    {
        const int n4 = Bsz * Msl * DIN / 4;
        cvt_tf32<<<(n4 + 255) / 256, 256>>>((const float4*)x, (float4*)x_tf, n4);
    }

    dim3 blk(256);

    // Layer 1: per m, h[b, n] = rna(relu(x[b,:] @ W1 + b1))
    dim3 g1(DH / BN, Bsz / BM, Msl);
    gemm_tf32<true, true><<<g1, blk, SMEM_DYN>>>(
        x_tf, W1, b1, h, DIN,
        /*aBatch*/ (long)DIN,        /*lda*/ Msl * DIN,
        /*wBatch*/ (long)DIN * DH,   /*ldw*/ DH,
        /*biasBatch*/ (long)DH,
        /*cBatch*/ (long)Bsz * DH,   /*ldc*/ DH);

    // Layer 2: per m, out[b, n] = h[b,:] @ W2 + b2
    dim3 g2(DOUT / BN, Bsz / BM, Msl);
    gemm_tf32<false, false><<<g2, blk, SMEM_DYN>>>(
        h, W2, b2, out, DH,
        /*aBatch*/ (long)Bsz * DH,   /*lda*/ DH,
        /*wBatch*/ (long)DH * DOUT,  /*ldw*/ DOUT,
        /*biasBatch*/ (long)DOUT,
        /*cBatch*/ (long)DOUT,       /*ldc*/ Msl * DOUT);
}

// round 11
// speedup vs baseline: 1.7048x; 1.7048x over previous
#include <cuda_runtime.h>
#include <cuda_fp16.h>
#include <cstdint>

namespace {

constexpr int Bsz = 512, Msl = 32, DIN = 1024, DH = 4096, DOUT = 1024;
constexpr int BM = 128, BN = 128, BK = 32;
constexpr int NBUF = 3;
constexpr int A_TILE = BM * BK * 2;       // 8 KB (fp16)
constexpr int B_TILE = BK * BN * 2;       // 8 KB (fp16, [k][n] natural)
constexpr int STAGE  = A_TILE + B_TILE;   // 16 KB
constexpr int SMEM_DYN = NBUF * STAGE;    // 48 KB -> 2 CTAs/SM

// Intermediate h: [m][b][dh], fp16 (11-bit significand, same as tf32).
__device__ __half g_h[(size_t)Bsz * Msl * DH];
// x converted to fp16 (pre-pass).
__device__ __half g_x_h[(size_t)Bsz * Msl * DIN];

__device__ __forceinline__ uint32_t smem_u32(const void* p) {
    uint32_t a;
    asm("{ .reg .u64 t; cvta.to.shared.u64 t, %1; cvt.u32.u64 %0, t; }" : "=r"(a) : "l"(p));
    return a;
}
__device__ __forceinline__ void cp16(uint32_t dst, const void* src) {
    asm volatile("cp.async.cg.shared.global [%0], [%1], 16;" :: "r"(dst), "l"(src));
}
#define CP_COMMIT() asm volatile("cp.async.commit_group;" ::: "memory")
#define CP_WAIT0()  asm volatile("cp.async.wait_group 0;" ::: "memory")
#define CP_WAIT1()  asm volatile("cp.async.wait_group 1;" ::: "memory")

__device__ __forceinline__ void ldsm4(uint32_t r[4], uint32_t addr) {
    asm volatile("ldmatrix.sync.aligned.m8n8.x4.shared.b16 {%0,%1,%2,%3}, [%4];"
                 : "=r"(r[0]), "=r"(r[1]), "=r"(r[2]), "=r"(r[3]) : "r"(addr));
}
__device__ __forceinline__ void ldsm4t(uint32_t r[4], uint32_t addr) {
    asm volatile("ldmatrix.sync.aligned.m8n8.x4.trans.shared.b16 {%0,%1,%2,%3}, [%4];"
                 : "=r"(r[0]), "=r"(r[1]), "=r"(r[2]), "=r"(r[3]) : "r"(addr));
}
__device__ __forceinline__ void mma_f16(float acc[4], const uint32_t a[4],
                                        uint32_t b0, uint32_t b1) {
    asm volatile(
        "mma.sync.aligned.m16n8k16.row.col.f32.f16.f16.f32 "
        "{%0,%1,%2,%3}, {%4,%5,%6,%7}, {%8,%9}, {%0,%1,%2,%3};\n"
        : "+f"(acc[0]), "+f"(acc[1]), "+f"(acc[2]), "+f"(acc[3])
        : "r"(a[0]), "r"(a[1]), "r"(a[2]), "r"(a[3]), "r"(b0), "r"(b1));
}
__device__ __forceinline__ uint32_t h2bits(__half2 h) {
    return *reinterpret_cast<uint32_t*>(&h);
}

// Pre-pass: x fp32 -> fp16.
__global__ void __launch_bounds__(256)
cvt_f16(const float4* __restrict__ in, uint2* __restrict__ out, int n4) {
    int i = blockIdx.x * blockDim.x + threadIdx.x;
    if (i < n4) {
        float4 v = in[i];
        uint2 o;
        o.x = h2bits(__floats2half2_rn(v.x, v.y));
        o.y = h2bits(__floats2half2_rn(v.z, v.w));
        out[i] = o;
    }
}

// C[BM,BN] tile of A[*,K](fp16) x W[K,*](fp32->fp16) (+bias fp32, optional ReLU).
// A: cp.async fp16, smem [m][k] 64B rows, swizzle g^=((m>>1)&3).
// W: LDG fp32 + cvt + STS, smem NATURAL [k][n] 256B rows, swizzle g^=(k&7);
//    B fragments via ldmatrix.x4.trans (hardware transpose).
// OUT_HALF: store C as fp16 (h for layer 2); else fp32.
template<bool RELU, bool OUT_HALF>
__global__ void __launch_bounds__(256, 2)
gemm_f16(const __half* __restrict__ Ag, const float* __restrict__ Wg,
         const float* __restrict__ biasg, void* __restrict__ Cg,
         int K,
         long aBatch, int lda, long wBatch, int ldw,
         long biasBatch, long cBatch, int ldc)
{
    extern __shared__ char sm[];
    const uint32_t sb = smem_u32(sm);

    const int tid  = threadIdx.x;
    const int lane = tid & 31, warp = tid >> 5;
    const int g = lane >> 2, tg = lane & 3;
    const int wm = warp & 3, wn = warp >> 2;          // 4 (m) x 2 (n) warps

    const int m0 = blockIdx.y * BM;
    const int n0 = blockIdx.x * BN;
    const __half* A   = Ag    + (size_t)blockIdx.z * aBatch;
    const float* W    = Wg    + (size_t)blockIdx.z * wBatch;
    const float* bias = biasg + (size_t)blockIdx.z * biasBatch;

    // ---- A cp.async: 128 rows x 64B; 256 threads x 2 cp16 ----
    const int a_kg = tid & 3;                 // 16B group in 64B row
    const int a_r  = tid >> 2;                // 0..63 (+64)
    const __half* a_src0 = A + (size_t)(m0 + a_r) * lda + a_kg * 8;
    const __half* a_src1 = a_src0 + (size_t)64 * lda;
    const uint32_t a_dst0 = sb + (uint32_t)(a_r * 64 + ((a_kg ^ ((a_r >> 1) & 3)) << 4));

    // ---- B: W row k = tid>>3 (32 rows), n-span (tid&7)*16 floats ----
    const int b_k  = tid >> 3;
    const int b_nb = (tid & 7) * 2;           // 16B-granule pair base
    const float* w_src = W + (size_t)b_k * ldw + n0 + (tid & 7) * 16;
    const size_t w_step = (size_t)BK * ldw;
    const uint32_t b_dst0 = (uint32_t)(b_k * 256 + (((b_nb)     ^ (b_k & 7)) << 4));
    const uint32_t b_dst1 = (uint32_t)(b_k * 256 + (((b_nb + 1) ^ (b_k & 7)) << 4));

    // ---- ldmatrix per-thread addresses ----
    const int lrow = lane & 15;
    const int lkh  = (lane >> 4) << 4;        // A: 0/16B k-half
    // A (non-trans): row = wm*32 + mt*16 + lrow; kb = ks*32 + lkh; g^=((row>>1)&3)
    const uint32_t sA = (uint32_t)(((lrow >> 1) & 3) << 4);
    const uint32_t warpA = sb + (uint32_t)((wm * 32 + lrow) * 64);
    // B (trans): krow = ks*16 + lrow; granule = wn*8 + (lane>>4) + ng*2, ^ (lrow&7)
    const int nbase = wn * 8 + (lane >> 4);
    uint32_t boff[4];
    #pragma unroll
    for (int ng = 0; ng < 4; ++ng)
        boff[ng] = (uint32_t)(lrow * 256 + (((nbase + ng * 2) ^ (lrow & 7)) << 4));

    float acc[2][8][4];
    #pragma unroll
    for (int i = 0; i < 2; i++)
        #pragma unroll
        for (int j = 0; j < 8; j++)
            #pragma unroll
            for (int q = 0; q < 4; q++) acc[i][j][q] = 0.f;

    float4 rb[4];

    auto cpA = [&](int k0, int buf) {
        const uint32_t d = a_dst0 + buf * STAGE;
        cp16(d,        a_src0 + k0);
        cp16(d + 4096, a_src1 + k0);
    };
    auto ldgB = [&]() {
        rb[0] = *(const float4*)(w_src);
        rb[1] = *(const float4*)(w_src + 4);
        rb[2] = *(const float4*)(w_src + 8);
        rb[3] = *(const float4*)(w_src + 12);
        w_src += w_step;
    };
    auto stsB = [&](int buf) {
        uint4 lo, hi;
        lo.x = h2bits(__floats2half2_rn(rb[0].x, rb[0].y));
        lo.y = h2bits(__floats2half2_rn(rb[0].z, rb[0].w));
        lo.z = h2bits(__floats2half2_rn(rb[1].x, rb[1].y));
        lo.w = h2bits(__floats2half2_rn(rb[1].z, rb[1].w));
        hi.x = h2bits(__floats2half2_rn(rb[2].x, rb[2].y));
        hi.y = h2bits(__floats2half2_rn(rb[2].z, rb[2].w));
        hi.z = h2bits(__floats2half2_rn(rb[3].x, rb[3].y));
        hi.w = h2bits(__floats2half2_rn(rb[3].z, rb[3].w));
        char* bb = sm + buf * STAGE + A_TILE;
        *(uint4*)(bb + b_dst0) = lo;
        *(uint4*)(bb + b_dst1) = hi;
    };

    auto compute = [&](int buf) {
        const uint32_t Ab = warpA + buf * STAGE;
        const uint32_t Bb = sb + buf * STAGE + A_TILE;
        #pragma unroll
        for (int ks = 0; ks < 2; ++ks) {           // two k16 steps
            const uint32_t kb = (uint32_t)(ks * 32 + lkh);
            uint32_t af[2][4];
            ldsm4(af[0], Ab +        (kb ^ sA));
            ldsm4(af[1], Ab + 1024 + (kb ^ sA));
            uint32_t bf[4][4];
            const uint32_t Bk = Bb + ks * 4096;
            ldsm4t(bf[0], Bk + boff[0]);
            ldsm4t(bf[1], Bk + boff[1]);
            ldsm4t(bf[2], Bk + boff[2]);
            ldsm4t(bf[3], Bk + boff[3]);
            #pragma unroll
            for (int mt = 0; mt < 2; ++mt)
                #pragma unroll
                for (int nt = 0; nt < 8; ++nt)
                    mma_f16(acc[mt][nt], af[mt],
                            bf[nt >> 1][(nt & 1) * 2], bf[nt >> 1][(nt & 1) * 2 + 1]);
        }
    };

    const int S = K / BK;

    // Preamble (round-9 cadence): A 2 ahead, B 2 ahead (1 smem + 1 regs)
    cpA(0, 0); CP_COMMIT();
    cpA(BK, 1); CP_COMMIT();
    ldgB();
    stsB(0);
    ldgB();
    CP_WAIT1();
    __syncthreads();

    #pragma unroll 1
    for (int s = 0; s < S; ++s) {
        const int buf  = s % NBUF;
        const int buf1 = (s + 1) % NBUF;
        const int buf2 = (s + 2) % NBUF;

        compute(buf);

        if (s + 1 < S) stsB(buf1);
        if (s + 2 < S) {
            ldgB();
            cpA((s + 2) * BK, buf2); CP_COMMIT();
            CP_WAIT1();
        } else if (s + 1 < S) {
            CP_WAIT0();
        }
        __syncthreads();
    }

    // Epilogue: +bias (fp32), optional relu; store fp16 (h) or fp32 (out).
    #pragma unroll
    for (int mt = 0; mt < 2; ++mt) {
        const int r = m0 + wm * 32 + mt * 16 + g;
        #pragma unroll
        for (int nt = 0; nt < 8; ++nt) {
            const int c = n0 + wn * 64 + nt * 8 + tg * 2;
            const float b0v = bias[c], b1v = bias[c + 1];
            float v0 = acc[mt][nt][0] + b0v;
            float v1 = acc[mt][nt][1] + b1v;
            float v2 = acc[mt][nt][2] + b0v;
            float v3 = acc[mt][nt][3] + b1v;
            if (RELU) {
                v0 = fmaxf(v0, 0.f); v1 = fmaxf(v1, 0.f);
                v2 = fmaxf(v2, 0.f); v3 = fmaxf(v3, 0.f);
            }
            if (OUT_HALF) {
                __half* C = (__half*)Cg + (size_t)blockIdx.z * cBatch;
                *(__half2*)(C + (size_t)r * ldc + c)       = __floats2half2_rn(v0, v1);
                *(__half2*)(C + (size_t)(r + 8) * ldc + c) = __floats2half2_rn(v2, v3);
            } else {
                float* C = (float*)Cg + (size_t)blockIdx.z * cBatch;
                float2 p0; p0.x = v0; p0.y = v1;
                float2 p1; p1.x = v2; p1.y = v3;
                *(float2*)(C + (size_t)r * ldc + c)       = p0;
                *(float2*)(C + (size_t)(r + 8) * ldc + c) = p1;
            }
        }
    }
}

} // anonymous namespace

extern "C" void kernel_launch(void* const* d_in, const int* in_sizes, int n_in,
                              void* d_out, int out_size) {
    (void)in_sizes; (void)n_in; (void)out_size;
    const float* x  = (const float*)d_in[0];  // [B, M, DIN]
    const float* W1 = (const float*)d_in[1];  // [M, DIN, DH]
    const float* b1 = (const float*)d_in[2];  // [M, DH]
    const float* W2 = (const float*)d_in[3];  // [M, DH, DOUT]
    const float* b2 = (const float*)d_in[4];  // [M, DOUT]
    float* out = (float*)d_out;               // [B, M, DOUT]

    __half* h = nullptr;
    cudaGetSymbolAddress((void**)&h, g_h);
    __half* x_h = nullptr;
    cudaGetSymbolAddress((void**)&x_h, g_x_h);

    cudaFuncSetAttribute(gemm_f16<true, true>,   cudaFuncAttributeMaxDynamicSharedMemorySize, SMEM_DYN);
    cudaFuncSetAttribute(gemm_f16<false, false>, cudaFuncAttributeMaxDynamicSharedMemorySize, SMEM_DYN);

    // Pre-pass: x -> fp16 (~8 us)
    {
        const int n4 = Bsz * Msl * DIN / 4;
        cvt_f16<<<(n4 + 255) / 256, 256>>>((const float4*)x, (uint2*)x_h, n4);
    }

    dim3 blk(256);

    // Layer 1: per m, h[b, n] = fp16(relu(x[b,:] @ W1 + b1))
    dim3 g1(DH / BN, Bsz / BM, Msl);
    gemm_f16<true, true><<<g1, blk, SMEM_DYN>>>(
        x_h, W1, b1, h, DIN,
        /*aBatch*/ (long)DIN,        /*lda*/ Msl * DIN,
        /*wBatch*/ (long)DIN * DH,   /*ldw*/ DH,
        /*biasBatch*/ (long)DH,
        /*cBatch*/ (long)Bsz * DH,   /*ldc*/ DH);

    // Layer 2: per m, out[b, n] = h[b,:] @ W2 + b2 (fp32 out)
    dim3 g2(DOUT / BN, Bsz / BM, Msl);
    gemm_f16<false, false><<<g2, blk, SMEM_DYN>>>(
        h, W2, b2, out, DH,
        /*aBatch*/ (long)Bsz * DH,   /*lda*/ DH,
        /*wBatch*/ (long)DH * DOUT,  /*ldw*/ DOUT,
        /*biasBatch*/ (long)DOUT,
        /*cBatch*/ (long)DOUT,       /*ldc*/ Msl * DOUT);
}

// round 12
// speedup vs baseline: 1.9183x; 1.1252x over previous
#include <cuda_runtime.h>
#include <cuda_fp16.h>
#include <cstdint>

namespace {

constexpr int Bsz = 512, Msl = 32, DIN = 1024, DH = 4096, DOUT = 1024;
constexpr int BM = 256, BN = 128, BK = 32;
constexpr int TPB = 512;
constexpr int NBUF = 3;
constexpr int A_TILE = BM * BK * 2;       // 16 KB (fp16, [m][k] 64B rows)
constexpr int B_TILE = BK * BN * 2;       // 8 KB  (fp16, [k][n] 256B rows)
constexpr int STAGE  = A_TILE + B_TILE;   // 24 KB
constexpr int SMEM_DYN = NBUF * STAGE;    // 72 KB

// Intermediate h: [m][b][dh], fp16 (11-bit significand, same as tf32).
__device__ __half g_h[(size_t)Bsz * Msl * DH];
// x converted to fp16 (pre-pass).
__device__ __half g_x_h[(size_t)Bsz * Msl * DIN];

__device__ __forceinline__ uint32_t smem_u32(const void* p) {
    uint32_t a;
    asm("{ .reg .u64 t; cvta.to.shared.u64 t, %1; cvt.u32.u64 %0, t; }" : "=r"(a) : "l"(p));
    return a;
}
__device__ __forceinline__ void cp16(uint32_t dst, const void* src) {
    asm volatile("cp.async.cg.shared.global [%0], [%1], 16;" :: "r"(dst), "l"(src));
}
#define CP_COMMIT() asm volatile("cp.async.commit_group;" ::: "memory")
#define CP_WAIT0()  asm volatile("cp.async.wait_group 0;" ::: "memory")
#define CP_WAIT1()  asm volatile("cp.async.wait_group 1;" ::: "memory")

__device__ __forceinline__ void ldsm4(uint32_t r[4], uint32_t addr) {
    asm volatile("ldmatrix.sync.aligned.m8n8.x4.shared.b16 {%0,%1,%2,%3}, [%4];"
                 : "=r"(r[0]), "=r"(r[1]), "=r"(r[2]), "=r"(r[3]) : "r"(addr));
}
__device__ __forceinline__ void ldsm4t(uint32_t r[4], uint32_t addr) {
    asm volatile("ldmatrix.sync.aligned.m8n8.x4.trans.shared.b16 {%0,%1,%2,%3}, [%4];"
                 : "=r"(r[0]), "=r"(r[1]), "=r"(r[2]), "=r"(r[3]) : "r"(addr));
}
__device__ __forceinline__ void mma_f16(float acc[4], const uint32_t a[4],
                                        uint32_t b0, uint32_t b1) {
    asm volatile(
        "mma.sync.aligned.m16n8k16.row.col.f32.f16.f16.f32 "
        "{%0,%1,%2,%3}, {%4,%5,%6,%7}, {%8,%9}, {%0,%1,%2,%3};\n"
        : "+f"(acc[0]), "+f"(acc[1]), "+f"(acc[2]), "+f"(acc[3])
        : "r"(a[0]), "r"(a[1]), "r"(a[2]), "r"(a[3]), "r"(b0), "r"(b1));
}
__device__ __forceinline__ uint32_t h2bits(__half2 h) {
    return *reinterpret_cast<uint32_t*>(&h);
}

// Pre-pass: x fp32 -> fp16.
__global__ void __launch_bounds__(256)
cvt_f16(const float4* __restrict__ in, uint2* __restrict__ out, int n4) {
    int i = blockIdx.x * blockDim.x + threadIdx.x;
    if (i < n4) {
        float4 v = in[i];
        uint2 o;
        o.x = h2bits(__floats2half2_rn(v.x, v.y));
        o.y = h2bits(__floats2half2_rn(v.z, v.w));
        out[i] = o;
    }
}

// C[BM=256,BN=128] tile of A[*,K](fp16) x W[K,*](fp32->fp16), +bias, opt ReLU.
// 512 threads, 16 warps as 4(m) x 4(n); warp tile 64x32.
// A: cp.async fp16, smem [m][k] 64B rows, swizzle g^=((m>>1)&3).
// W: LDG fp32 + cvt + STS, smem natural [k][n] 256B rows, swizzle g^=(k&7);
//    fragments via ldmatrix.x4.trans.
template<bool RELU, bool OUT_HALF>
__global__ void __launch_bounds__(TPB, 1)
gemm_f16(const __half* __restrict__ Ag, const float* __restrict__ Wg,
         const float* __restrict__ biasg, void* __restrict__ Cg,
         int K,
         long aBatch, int lda, long wBatch, int ldw,
         long biasBatch, long cBatch, int ldc)
{
    extern __shared__ char sm[];
    const uint32_t sb = smem_u32(sm);

    const int tid  = threadIdx.x;
    const int lane = tid & 31, warp = tid >> 5;
    const int g = lane >> 2, tg = lane & 3;
    const int wm = warp & 3, wn = warp >> 2;          // 4 (m) x 4 (n)

    const int m0 = blockIdx.y * BM;
    const int n0 = blockIdx.x * BN;
    const __half* A   = Ag    + (size_t)blockIdx.z * aBatch;
    const float* W    = Wg    + (size_t)blockIdx.z * wBatch;
    const float* bias = biasg + (size_t)blockIdx.z * biasBatch;

    // ---- A cp.async: 256 rows x 64B = 1024 cp16; 512 threads x 2 ----
    const int a_kg = tid & 3;                 // 16B group in 64B row
    const int a_r  = tid >> 2;                // 0..127 (+128)
    const __half* a_src0 = A + (size_t)(m0 + a_r) * lda + a_kg * 8;
    const __half* a_src1 = a_src0 + (size_t)128 * lda;
    const uint32_t a_dst0 = sb + (uint32_t)(a_r * 64 + ((a_kg ^ ((a_r >> 1) & 3)) << 4));

    // ---- B: row k = tid>>4 (0..31), granule g = tid&15 (8 floats) ----
    const int b_k = tid >> 4;
    const int b_g = tid & 15;
    const float* w_src = W + (size_t)b_k * ldw + n0 + b_g * 8;
    const size_t w_step = (size_t)BK * ldw;
    const uint32_t b_dst = (uint32_t)(b_k * 256 + ((b_g ^ (b_k & 7)) << 4));

    // ---- ldmatrix per-thread addresses ----
    const int lrow = lane & 15;
    const int lkh  = (lane >> 4) << 4;        // A: 0/16B k-half
    const uint32_t sA = (uint32_t)(((lrow >> 1) & 3) << 4);
    const uint32_t warpA = sb + (uint32_t)((wm * 64 + lrow) * 64);
    // B trans: krow = ks*16 + lrow; granules wn*4 + ng*2 + (lane>>4), ^ (lrow&7)
    const int nbase = wn * 4 + (lane >> 4);
    uint32_t boff[2];
    #pragma unroll
    for (int ng = 0; ng < 2; ++ng)
        boff[ng] = (uint32_t)(lrow * 256 + (((nbase + ng * 2) ^ (lrow & 7)) << 4));

    float acc[4][4][4];
    #pragma unroll
    for (int i = 0; i < 4; i++)
        #pragma unroll
        for (int j = 0; j < 4; j++)
            #pragma unroll
            for (int q = 0; q < 4; q++) acc[i][j][q] = 0.f;

    float4 rb0, rb1;

    auto cpA = [&](int k0, int buf) {
        const uint32_t d = a_dst0 + buf * STAGE;
        cp16(d,        a_src0 + k0);
        cp16(d + 8192, a_src1 + k0);
    };
    auto ldgB = [&]() {
        rb0 = *(const float4*)(w_src);
        rb1 = *(const float4*)(w_src + 4);
        w_src += w_step;
    };
    auto stsB = [&](int buf) {
        uint4 v;
        v.x = h2bits(__floats2half2_rn(rb0.x, rb0.y));
        v.y = h2bits(__floats2half2_rn(rb0.z, rb0.w));
        v.z = h2bits(__floats2half2_rn(rb1.x, rb1.y));
        v.w = h2bits(__floats2half2_rn(rb1.z, rb1.w));
        *(uint4*)(sm + buf * STAGE + A_TILE + b_dst) = v;
    };

    auto compute = [&](int buf) {
        const uint32_t Ab = warpA + buf * STAGE;
        const uint32_t Bb = sb + buf * STAGE + A_TILE;
        #pragma unroll
        for (int ks = 0; ks < 2; ++ks) {           // two k16 steps
            const uint32_t kb = (uint32_t)(ks * 32 + lkh);
            uint32_t af[4][4];
            #pragma unroll
            for (int mt = 0; mt < 4; ++mt)
                ldsm4(af[mt], Ab + mt * 1024 + (kb ^ sA));
            uint32_t bf[2][4];
            const uint32_t Bk = Bb + ks * 4096;
            ldsm4t(bf[0], Bk + boff[0]);
            ldsm4t(bf[1], Bk + boff[1]);
            #pragma unroll
            for (int mt = 0; mt < 4; ++mt)
                #pragma unroll
                for (int nt = 0; nt < 4; ++nt)
                    mma_f16(acc[mt][nt], af[mt],
                            bf[nt >> 1][(nt & 1) * 2], bf[nt >> 1][(nt & 1) * 2 + 1]);
        }
    };

    const int S = K / BK;

    // Preamble: A 2 stages ahead (async), B 2 ahead (1 smem + 1 regs)
    cpA(0, 0); CP_COMMIT();
    cpA(BK, 1); CP_COMMIT();
    ldgB();
    stsB(0);
    ldgB();
    CP_WAIT1();
    __syncthreads();

    #pragma unroll 1
    for (int s = 0; s < S; ++s) {
        const int buf  = s % NBUF;
        const int buf1 = (s + 1) % NBUF;
        const int buf2 = (s + 2) % NBUF;

        compute(buf);

        if (s + 1 < S) stsB(buf1);
        if (s + 2 < S) {
            ldgB();
            cpA((s + 2) * BK, buf2); CP_COMMIT();
            CP_WAIT1();
        } else if (s + 1 < S) {
            CP_WAIT0();
        }
        __syncthreads();
    }

    // Epilogue: +bias (fp32), optional relu; store fp16 (h) or fp32 (out).
    #pragma unroll
    for (int mt = 0; mt < 4; ++mt) {
        const int r = m0 + wm * 64 + mt * 16 + g;
        #pragma unroll
        for (int nt = 0; nt < 4; ++nt) {
            const int c = n0 + wn * 32 + nt * 8 + tg * 2;
            const float b0v = bias[c], b1v = bias[c + 1];
            float v0 = acc[mt][nt][0] + b0v;
            float v1 = acc[mt][nt][1] + b1v;
            float v2 = acc[mt][nt][2] + b0v;
            float v3 = acc[mt][nt][3] + b1v;
            if (RELU) {
                v0 = fmaxf(v0, 0.f); v1 = fmaxf(v1, 0.f);
                v2 = fmaxf(v2, 0.f); v3 = fmaxf(v3, 0.f);
            }
            if (OUT_HALF) {
                __half* C = (__half*)Cg + (size_t)blockIdx.z * cBatch;
                *(__half2*)(C + (size_t)r * ldc + c)       = __floats2half2_rn(v0, v1);
                *(__half2*)(C + (size_t)(r + 8) * ldc + c) = __floats2half2_rn(v2, v3);
            } else {
                float* C = (float*)Cg + (size_t)blockIdx.z * cBatch;
                float2 p0; p0.x = v0; p0.y = v1;
                float2 p1; p1.x = v2; p1.y = v3;
                *(float2*)(C + (size_t)r * ldc + c)       = p0;
                *(float2*)(C + (size_t)(r + 8) * ldc + c) = p1;
            }
        }
    }
}

} // anonymous namespace

extern "C" void kernel_launch(void* const* d_in, const int* in_sizes, int n_in,
                              void* d_out, int out_size) {
    (void)in_sizes; (void)n_in; (void)out_size;
    const float* x  = (const float*)d_in[0];  // [B, M, DIN]
    const float* W1 = (const float*)d_in[1];  // [M, DIN, DH]
    const float* b1 = (const float*)d_in[2];  // [M, DH]
    const float* W2 = (const float*)d_in[3];  // [M, DH, DOUT]
    const float* b2 = (const float*)d_in[4];  // [M, DOUT]
    float* out = (float*)d_out;               // [B, M, DOUT]

    __half* h = nullptr;
    cudaGetSymbolAddress((void**)&h, g_h);
    __half* x_h = nullptr;
    cudaGetSymbolAddress((void**)&x_h, g_x_h);

    cudaFuncSetAttribute(gemm_f16<true, true>,   cudaFuncAttributeMaxDynamicSharedMemorySize, SMEM_DYN);
    cudaFuncSetAttribute(gemm_f16<false, false>, cudaFuncAttributeMaxDynamicSharedMemorySize, SMEM_DYN);

    // Pre-pass: x -> fp16 (~18 us)
    {
        const int n4 = Bsz * Msl * DIN / 4;
        cvt_f16<<<(n4 + 255) / 256, 256>>>((const float4*)x, (uint2*)x_h, n4);
    }

    dim3 blk(TPB);

    // Layer 1: per m, h[b, n] = fp16(relu(x[b,:] @ W1 + b1))
    dim3 g1(DH / BN, Bsz / BM, Msl);
    gemm_f16<true, true><<<g1, blk, SMEM_DYN>>>(
        x_h, W1, b1, h, DIN,
        /*aBatch*/ (long)DIN,        /*lda*/ Msl * DIN,
        /*wBatch*/ (long)DIN * DH,   /*ldw*/ DH,
        /*biasBatch*/ (long)DH,
        /*cBatch*/ (long)Bsz * DH,   /*ldc*/ DH);

    // Layer 2: per m, out[b, n] = h[b,:] @ W2 + b2 (fp32 out)
    dim3 g2(DOUT / BN, Bsz / BM, Msl);
    gemm_f16<false, false><<<g2, blk, SMEM_DYN>>>(
        h, W2, b2, out, DH,
        /*aBatch*/ (long)Bsz * DH,   /*lda*/ DH,
        /*wBatch*/ (long)DH * DOUT,  /*ldw*/ DOUT,
        /*biasBatch*/ (long)DOUT,
        /*cBatch*/ (long)DOUT,       /*ldc*/ Msl * DOUT);
}

// round 13
// speedup vs baseline: 2.0562x; 1.0719x over previous
#include <cuda_runtime.h>
#include <cuda_fp16.h>
#include <cstdint>

namespace {

constexpr int Bsz = 512, Msl = 32, DIN = 1024, DH = 4096, DOUT = 1024;
constexpr int BM = 256, BN = 128, BK = 64;
constexpr int TPB = 512;
constexpr int NBUF = 3;
constexpr int A_TILE = BM * BK * 2;       // 32 KB (fp16, [m][k] 128B rows)
constexpr int B_TILE = BK * BN * 2;       // 16 KB (fp16, [k][n] 256B rows)
constexpr int STAGE  = A_TILE + B_TILE;   // 48 KB
constexpr int SMEM_DYN = NBUF * STAGE;    // 144 KB (1 CTA/SM)

// Intermediate h: [m][b][dh], fp16 (11-bit significand, same as tf32).
__device__ __half g_h[(size_t)Bsz * Msl * DH];
// x converted to fp16 (pre-pass).
__device__ __half g_x_h[(size_t)Bsz * Msl * DIN];

__device__ __forceinline__ uint32_t smem_u32(const void* p) {
    uint32_t a;
    asm("{ .reg .u64 t; cvta.to.shared.u64 t, %1; cvt.u32.u64 %0, t; }" : "=r"(a) : "l"(p));
    return a;
}
__device__ __forceinline__ void cp16(uint32_t dst, const void* src) {
    asm volatile("cp.async.cg.shared.global [%0], [%1], 16;" :: "r"(dst), "l"(src));
}
#define CP_COMMIT() asm volatile("cp.async.commit_group;" ::: "memory")
#define CP_WAIT0()  asm volatile("cp.async.wait_group 0;" ::: "memory")
#define CP_WAIT1()  asm volatile("cp.async.wait_group 1;" ::: "memory")

__device__ __forceinline__ void ldsm4(uint32_t r[4], uint32_t addr) {
    asm volatile("ldmatrix.sync.aligned.m8n8.x4.shared.b16 {%0,%1,%2,%3}, [%4];"
                 : "=r"(r[0]), "=r"(r[1]), "=r"(r[2]), "=r"(r[3]) : "r"(addr));
}
__device__ __forceinline__ void ldsm4t(uint32_t r[4], uint32_t addr) {
    asm volatile("ldmatrix.sync.aligned.m8n8.x4.trans.shared.b16 {%0,%1,%2,%3}, [%4];"
                 : "=r"(r[0]), "=r"(r[1]), "=r"(r[2]), "=r"(r[3]) : "r"(addr));
}
__device__ __forceinline__ void mma_f16(float acc[4], const uint32_t a[4],
                                        uint32_t b0, uint32_t b1) {
    asm volatile(
        "mma.sync.aligned.m16n8k16.row.col.f32.f16.f16.f32 "
        "{%0,%1,%2,%3}, {%4,%5,%6,%7}, {%8,%9}, {%0,%1,%2,%3};\n"
        : "+f"(acc[0]), "+f"(acc[1]), "+f"(acc[2]), "+f"(acc[3])
        : "r"(a[0]), "r"(a[1]), "r"(a[2]), "r"(a[3]), "r"(b0), "r"(b1));
}
__device__ __forceinline__ uint32_t h2bits(__half2 h) {
    return *reinterpret_cast<uint32_t*>(&h);
}

// Pre-pass: x fp32 -> fp16.
__global__ void __launch_bounds__(256)
cvt_f16(const float4* __restrict__ in, uint2* __restrict__ out, int n4) {
    int i = blockIdx.x * blockDim.x + threadIdx.x;
    if (i < n4) {
        float4 v = in[i];
        uint2 o;
        o.x = h2bits(__floats2half2_rn(v.x, v.y));
        o.y = h2bits(__floats2half2_rn(v.z, v.w));
        out[i] = o;
    }
}

// C[BM=256,BN=128] tile of A[*,K](fp16) x W[K,*](fp32->fp16), +bias, opt ReLU.
// 512 threads, 16 warps as 4(m) x 4(n); warp tile 64x32. BK=64 per stage.
// A: cp.async fp16, smem [m][k] 128B rows, swizzle g^=(m&7).
// W: LDG fp32 + cvt + STS, smem natural [k][n] 256B rows, swizzle g^=(k&7);
//    fragments via ldmatrix.x4.trans.
template<bool RELU, bool OUT_HALF>
__global__ void __launch_bounds__(TPB, 1)
gemm_f16(const __half* __restrict__ Ag, const float* __restrict__ Wg,
         const float* __restrict__ biasg, void* __restrict__ Cg,
         int K,
         long aBatch, int lda, long wBatch, int ldw,
         long biasBatch, long cBatch, int ldc)
{
    extern __shared__ char sm[];
    const uint32_t sb = smem_u32(sm);

    const int tid  = threadIdx.x;
    const int lane = tid & 31, warp = tid >> 5;
    const int g = lane >> 2, tg = lane & 3;
    const int wm = warp & 3, wn = warp >> 2;          // 4 (m) x 4 (n)

    const int m0 = blockIdx.y * BM;
    const int n0 = blockIdx.x * BN;
    const __half* A   = Ag    + (size_t)blockIdx.z * aBatch;
    const float* W    = Wg    + (size_t)blockIdx.z * wBatch;
    const float* bias = biasg + (size_t)blockIdx.z * biasBatch;

    // ---- A cp.async: 256 rows x 128B = 2048 cp16; 512 threads x 4 ----
    const int a_kg = tid & 7;                 // 16B granule in 128B row
    const int a_r  = tid >> 3;                // 0..63 (+64,+128,+192)
    const __half* a_src = A + (size_t)(m0 + a_r) * lda + a_kg * 8;
    const size_t a_rstep = (size_t)64 * lda;
    const uint32_t a_dst = sb + (uint32_t)(a_r * 128 + ((a_kg ^ (a_r & 7)) << 4));

    // ---- B: row r = tid>>4 (0..31, +32), granule gr = tid&15 ----
    const int b_r  = tid >> 4;
    const int b_gr = tid & 15;
    const float* w_src = W + (size_t)b_r * ldw + n0 + b_gr * 8;
    const size_t w_step = (size_t)BK * ldw;
    const size_t w_half = (size_t)32 * ldw;
    const uint32_t b_dst = (uint32_t)(b_r * 256 + ((b_gr ^ (b_r & 7)) << 4));

    // ---- ldmatrix per-thread addresses ----
    const int lrow = lane & 15;
    // A (non-trans): row = wm*64 + mt*16 + lrow (row&7 == lrow&7);
    // granule = ks*2 + (lane>>4), xor (lrow&7)
    const uint32_t warpA = sb + (uint32_t)((wm * 64 + lrow) * 128);
    uint32_t aoff[4];
    #pragma unroll
    for (int ks = 0; ks < 4; ++ks)
        aoff[ks] = (uint32_t)(((ks * 2 + (lane >> 4)) ^ (lrow & 7)) << 4);
    // B (trans): krow = ks*16 + lrow; granules wn*4 + ng*2 + (lane>>4), ^ (lrow&7)
    const int nbase = wn * 4 + (lane >> 4);
    uint32_t boff[2];
    #pragma unroll
    for (int ng = 0; ng < 2; ++ng)
        boff[ng] = (uint32_t)(lrow * 256 + (((nbase + ng * 2) ^ (lrow & 7)) << 4));

    float acc[4][4][4];
    #pragma unroll
    for (int i = 0; i < 4; i++)
        #pragma unroll
        for (int j = 0; j < 4; j++)
            #pragma unroll
            for (int q = 0; q < 4; q++) acc[i][j][q] = 0.f;

    float4 rb0, rb1;

    auto cpA = [&](int k0, int buf) {
        const uint32_t d = a_dst + buf * STAGE;
        cp16(d,         a_src + k0);
        cp16(d + 8192,  a_src + k0 + a_rstep);
        cp16(d + 16384, a_src + k0 + 2 * a_rstep);
        cp16(d + 24576, a_src + k0 + 3 * a_rstep);
    };
    auto ldgB = [&]() {
        rb0 = *(const float4*)(w_src);
        rb1 = *(const float4*)(w_src + w_half);
        w_src += w_step;
    };
    auto stsB = [&](int buf) {
        uint4 v0, v1;
        v0.x = h2bits(__floats2half2_rn(rb0.x, rb0.y));
        v0.y = h2bits(__floats2half2_rn(rb0.z, rb0.w));
        const float4 q0 = *(const float4*)(w_src - w_step + 4);
        // NOTE: second half of each 8-float slice loaded here would add LDG to
        // the critical path; instead rb0/rb1 hold floats 0..3 and the 4..7 come
        // from a second pair kept in rc0/rc1 (see ldgB2/stsB packing below).
        (void)q0;
        v0.z = 0; v0.w = 0; v1.x = 0; v1.y = 0; v1.z = 0; v1.w = 0;
        (void)v1; (void)buf;
    };
    (void)stsB; // replaced by explicit code below (kept lambda slot for clarity)

    // rb/rc hold 8 floats per row-slice: rb = floats 0..3, rc = floats 4..7
    float4 rc0, rc1;
    auto ldgB8 = [&]() {
        rb0 = *(const float4*)(w_src);
        rc0 = *(const float4*)(w_src + 4);
        rb1 = *(const float4*)(w_src + w_half);
        rc1 = *(const float4*)(w_src + w_half + 4);
        w_src += w_step;
    };
    auto stsB8 = [&](int buf) {
        uint4 v0, v1;
        v0.x = h2bits(__floats2half2_rn(rb0.x, rb0.y));
        v0.y = h2bits(__floats2half2_rn(rb0.z, rb0.w));
        v0.z = h2bits(__floats2half2_rn(rc0.x, rc0.y));
        v0.w = h2bits(__floats2half2_rn(rc0.z, rc0.w));
        v1.x = h2bits(__floats2half2_rn(rb1.x, rb1.y));
        v1.y = h2bits(__floats2half2_rn(rb1.z, rb1.w));
        v1.z = h2bits(__floats2half2_rn(rc1.x, rc1.y));
        v1.w = h2bits(__floats2half2_rn(rc1.z, rc1.w));
        char* bb = sm + buf * STAGE + A_TILE;
        *(uint4*)(bb + b_dst)            = v0;
        *(uint4*)(bb + b_dst + 32 * 256) = v1;
    };

    auto compute = [&](int buf) {
        const uint32_t Ab = warpA + buf * STAGE;
        const uint32_t Bb = sb + buf * STAGE + A_TILE;
        #pragma unroll
        for (int ks = 0; ks < 4; ++ks) {           // four k16 steps
            uint32_t af[4][4];
            #pragma unroll
            for (int mt = 0; mt < 4; ++mt)
                ldsm4(af[mt], Ab + mt * 2048 + aoff[ks]);
            uint32_t bf[2][4];
            const uint32_t Bk = Bb + ks * 4096;
            ldsm4t(bf[0], Bk + boff[0]);
            ldsm4t(bf[1], Bk + boff[1]);
            #pragma unroll
            for (int mt = 0; mt < 4; ++mt)
                #pragma unroll
                for (int nt = 0; nt < 4; ++nt)
                    mma_f16(acc[mt][nt], af[mt],
                            bf[nt >> 1][(nt & 1) * 2], bf[nt >> 1][(nt & 1) * 2 + 1]);
        }
    };

    const int S = K / BK;

    // Preamble: A stages 0,1 async; B stage 0 in smem; B stage 1 in regs.
    cpA(0, 0); CP_COMMIT();
    cpA(BK, 1); CP_COMMIT();
    ldgB8();
    stsB8(0);
    ldgB8();
    CP_WAIT1();
    __syncthreads();

    #pragma unroll 1
    for (int s = 0; s < S; ++s) {
        const int buf  = s % NBUF;
        const int buf1 = (s + 1) % NBUF;
        const int buf2 = (s + 2) % NBUF;

        // producers first: retire under the MMA stream
        if (s + 1 < S) stsB8(buf1);                // rb/rc = stage s+1
        if (s + 2 < S) {
            ldgB8();                               // rb/rc <- stage s+2
            cpA((s + 2) * BK, buf2); CP_COMMIT();
        }

        compute(buf);

        if (s + 2 < S)      { CP_WAIT1(); }
        else if (s + 1 < S) { CP_WAIT0(); }
        __syncthreads();
    }

    // Epilogue: +bias (fp32), optional relu; store fp16 (h) or fp32 (out).
    #pragma unroll
    for (int mt = 0; mt < 4; ++mt) {
        const int r = m0 + wm * 64 + mt * 16 + g;
        #pragma unroll
        for (int nt = 0; nt < 4; ++nt) {
            const int c = n0 + wn * 32 + nt * 8 + tg * 2;
            const float b0v = bias[c], b1v = bias[c + 1];
            float v0 = acc[mt][nt][0] + b0v;
            float v1 = acc[mt][nt][1] + b1v;
            float v2 = acc[mt][nt][2] + b0v;
            float v3 = acc[mt][nt][3] + b1v;
            if (RELU) {
                v0 = fmaxf(v0, 0.f); v1 = fmaxf(v1, 0.f);
                v2 = fmaxf(v2, 0.f); v3 = fmaxf(v3, 0.f);
            }
            if (OUT_HALF) {
                __half* C = (__half*)Cg + (size_t)blockIdx.z * cBatch;
                *(__half2*)(C + (size_t)r * ldc + c)       = __floats2half2_rn(v0, v1);
                *(__half2*)(C + (size_t)(r + 8) * ldc + c) = __floats2half2_rn(v2, v3);
            } else {
                float* C = (float*)Cg + (size_t)blockIdx.z * cBatch;
                float2 p0; p0.x = v0; p0.y = v1;
                float2 p1; p1.x = v2; p1.y = v3;
                *(float2*)(C + (size_t)r * ldc + c)       = p0;
                *(float2*)(C + (size_t)(r + 8) * ldc + c) = p1;
            }
        }
    }
}

} // anonymous namespace

extern "C" void kernel_launch(void* const* d_in, const int* in_sizes, int n_in,
                              void* d_out, int out_size) {
    (void)in_sizes; (void)n_in; (void)out_size;
    const float* x  = (const float*)d_in[0];  // [B, M, DIN]
    const float* W1 = (const float*)d_in[1];  // [M, DIN, DH]
    const float* b1 = (const float*)d_in[2];  // [M, DH]
    const float* W2 = (const float*)d_in[3];  // [M, DH, DOUT]
    const float* b2 = (const float*)d_in[4];  // [M, DOUT]
    float* out = (float*)d_out;               // [B, M, DOUT]

    __half* h = nullptr;
    cudaGetSymbolAddress((void**)&h, g_h);
    __half* x_h = nullptr;
    cudaGetSymbolAddress((void**)&x_h, g_x_h);

    cudaFuncSetAttribute(gemm_f16<true, true>,   cudaFuncAttributeMaxDynamicSharedMemorySize, SMEM_DYN);
    cudaFuncSetAttribute(gemm_f16<false, false>, cudaFuncAttributeMaxDynamicSharedMemorySize, SMEM_DYN);

    // Pre-pass: x -> fp16 (~17 us)
    {
        const int n4 = Bsz * Msl * DIN / 4;
        cvt_f16<<<(n4 + 255) / 256, 256>>>((const float4*)x, (uint2*)x_h, n4);
    }

    dim3 blk(TPB);

    // Layer 1: per m, h[b, n] = fp16(relu(x[b,:] @ W1 + b1))
    dim3 g1(DH / BN, Bsz / BM, Msl);
    gemm_f16<true, true><<<g1, blk, SMEM_DYN>>>(
        x_h, W1, b1, h, DIN,
        /*aBatch*/ (long)DIN,        /*lda*/ Msl * DIN,
        /*wBatch*/ (long)DIN * DH,   /*ldw*/ DH,
        /*biasBatch*/ (long)DH,
        /*cBatch*/ (long)Bsz * DH,   /*ldc*/ DH);

    // Layer 2: per m, out[b, n] = h[b,:] @ W2 + b2 (fp32 out)
    dim3 g2(DOUT / BN, Bsz / BM, Msl);
    gemm_f16<false, false><<<g2, blk, SMEM_DYN>>>(
        h, W2, b2, out, DH,
        /*aBatch*/ (long)Bsz * DH,   /*lda*/ DH,
        /*wBatch*/ (long)DH * DOUT,  /*ldw*/ DOUT,
        /*biasBatch*/ (long)DOUT,
        /*cBatch*/ (long)DOUT,       /*ldc*/ Msl * DOUT);
}

// round 14
// speedup vs baseline: 2.2077x; 1.0737x over previous
#include <cuda_runtime.h>
#include <cuda_fp16.h>
#include <cstdint>

namespace {

constexpr int Bsz = 512, Msl = 32, DIN = 1024, DH = 4096, DOUT = 1024;
constexpr int BM = 256, BN = 128, BK = 128;
constexpr int TPB = 512;
constexpr int A_TILE = BM * BK * 2;       // 64 KB (fp16, [m][k] 256B rows)
constexpr int B_TILE = BK * BN * 2;       // 32 KB (fp16, [k][n] 256B rows)
constexpr int STAGE  = A_TILE + B_TILE;   // 96 KB
constexpr int SMEM_DYN = 2 * STAGE;       // 192 KB ping-pong (1 CTA/SM)

// Intermediate h: [m][b][dh], fp16 (11-bit significand, same as tf32).
__device__ __half g_h[(size_t)Bsz * Msl * DH];
// x converted to fp16 (pre-pass).
__device__ __half g_x_h[(size_t)Bsz * Msl * DIN];

__device__ __forceinline__ uint32_t smem_u32(const void* p) {
    uint32_t a;
    asm("{ .reg .u64 t; cvta.to.shared.u64 t, %1; cvt.u32.u64 %0, t; }" : "=r"(a) : "l"(p));
    return a;
}
__device__ __forceinline__ void cp16(uint32_t dst, const void* src) {
    asm volatile("cp.async.cg.shared.global [%0], [%1], 16;" :: "r"(dst), "l"(src));
}
#define CP_COMMIT() asm volatile("cp.async.commit_group;" ::: "memory")
#define CP_WAIT0()  asm volatile("cp.async.wait_group 0;" ::: "memory")

__device__ __forceinline__ void ldsm4(uint32_t r[4], uint32_t addr) {
    asm volatile("ldmatrix.sync.aligned.m8n8.x4.shared.b16 {%0,%1,%2,%3}, [%4];"
                 : "=r"(r[0]), "=r"(r[1]), "=r"(r[2]), "=r"(r[3]) : "r"(addr));
}
__device__ __forceinline__ void ldsm4t(uint32_t r[4], uint32_t addr) {
    asm volatile("ldmatrix.sync.aligned.m8n8.x4.trans.shared.b16 {%0,%1,%2,%3}, [%4];"
                 : "=r"(r[0]), "=r"(r[1]), "=r"(r[2]), "=r"(r[3]) : "r"(addr));
}
__device__ __forceinline__ void mma_f16(float acc[4], const uint32_t a[4],
                                        uint32_t b0, uint32_t b1) {
    asm volatile(
        "mma.sync.aligned.m16n8k16.row.col.f32.f16.f16.f32 "
        "{%0,%1,%2,%3}, {%4,%5,%6,%7}, {%8,%9}, {%0,%1,%2,%3};\n"
        : "+f"(acc[0]), "+f"(acc[1]), "+f"(acc[2]), "+f"(acc[3])
        : "r"(a[0]), "r"(a[1]), "r"(a[2]), "r"(a[3]), "r"(b0), "r"(b1));
}
__device__ __forceinline__ uint32_t h2bits(__half2 h) {
    return *reinterpret_cast<uint32_t*>(&h);
}

// Pre-pass: x fp32 -> fp16.
__global__ void __launch_bounds__(256)
cvt_f16(const float4* __restrict__ in, uint2* __restrict__ out, int n4) {
    int i = blockIdx.x * blockDim.x + threadIdx.x;
    if (i < n4) {
        float4 v = in[i];
        uint2 o;
        o.x = h2bits(__floats2half2_rn(v.x, v.y));
        o.y = h2bits(__floats2half2_rn(v.z, v.w));
        out[i] = o;
    }
}

// C[BM=256,BN=128] tile of A[*,K](fp16) x W[K,*](fp32->fp16), +bias, opt ReLU.
// 512 threads, 16 warps as 4(m) x 4(n); warp tile 64x32. BK=128 per stage,
// 2-stage smem ping-pong (96 KB/stage).
// A: cp.async fp16, smem [m][k] 256B rows, swizzle g^=(m&7), one batch/stage.
// W: staged in TWO halves (64 k-rows each) sharing one 16-reg set; per half:
//    LDG fp32 (pairwise-contiguous 512B slices) + cvt + conflict-free STS
//    (thread stores fp16 granules q and q+8 -> each 8-lane phase covers all
//    8 bank slots after the g^(k&7) swizzle). Fragments via ldmatrix.x4.trans.
template<bool RELU, bool OUT_HALF>
__global__ void __launch_bounds__(TPB, 1)
gemm_f16(const __half* __restrict__ Ag, const float* __restrict__ Wg,
         const float* __restrict__ biasg, void* __restrict__ Cg,
         int K,
         long aBatch, int lda, long wBatch, int ldw,
         long biasBatch, long cBatch, int ldc)
{
    extern __shared__ char sm[];
    const uint32_t sb = smem_u32(sm);

    const int tid  = threadIdx.x;
    const int lane = tid & 31, warp = tid >> 5;
    const int g = lane >> 2, tg = lane & 3;
    const int wm = warp & 3, wn = warp >> 2;          // 4 (m) x 4 (n)

    const int m0 = blockIdx.y * BM;
    const int n0 = blockIdx.x * BN;
    const __half* A   = Ag    + (size_t)blockIdx.z * aBatch;
    const float* W    = Wg    + (size_t)blockIdx.z * wBatch;
    const float* bias = biasg + (size_t)blockIdx.z * biasBatch;

    // ---- A cp.async: 256 rows x 256B = 4096 cp16; 512 threads x 8 ----
    const int a_kg = tid & 15;                // 16B granule in 256B row
    const int a_r  = tid >> 4;                // 0..31 (+32 x7)
    const __half* a_src = A + (size_t)(m0 + a_r) * lda + a_kg * 8;
    const size_t a_rstep = (size_t)32 * lda;
    const uint32_t a_dst = sb + (uint32_t)(a_r * 256 + ((a_kg ^ (a_r & 7)) << 4));

    // ---- B: fp32 row r = tid>>3 (0..63 per half), g = tid&7 ----
    // Thread owns fp16 granules q0 = g and q1 = g+8 of its row:
    // fp32 floats [8g..8g+7] and [8g+64..8g+71].
    const int b_r = tid >> 3;
    const int b_g = tid & 7;
    const float* w0 = W + (size_t)b_r * ldw + n0 + b_g * 8;
    const size_t w_stage = (size_t)BK * ldw;          // 128 k-rows
    const size_t w_half  = (size_t)64 * ldw;
    const uint32_t b_q0 = (uint32_t)(b_r * 256 + (((b_g)     ^ (b_r & 7)) << 4));
    const uint32_t b_q1 = (uint32_t)(b_r * 256 + (((b_g + 8) ^ (b_r & 7)) << 4));
    constexpr uint32_t BHALF = 64 * 256;              // half1 smem offset

    // ---- ldmatrix per-thread pieces ----
    const int lrow = lane & 15;
    const int lhi  = lane >> 4;
    const int lr7  = lrow & 7;
    const uint32_t warpA = sb + (uint32_t)((wm * 64 + lrow) * 256);
    const int nbase = wn * 4 + lhi;
    uint32_t boff[2];
    #pragma unroll
    for (int ng = 0; ng < 2; ++ng)
        boff[ng] = (uint32_t)(lrow * 256 + (((nbase + ng * 2) ^ lr7) << 4));

    float acc[4][4][4];
    #pragma unroll
    for (int i = 0; i < 4; i++)
        #pragma unroll
        for (int j = 0; j < 4; j++)
            #pragma unroll
            for (int q = 0; q < 4; q++) acc[i][j][q] = 0.f;

    float4 rb0, rb1, rc0, rc1;                        // one shared 16-reg B set

    auto cpA = [&](int s, int buf) {
        const __half* src = a_src + (size_t)s * BK;
        const uint32_t d = a_dst + buf * STAGE;
        #pragma unroll
        for (int it = 0; it < 8; ++it)
            cp16(d + it * 8192, src + it * a_rstep);
    };
    auto ldgB = [&](const float* p) {
        rb0 = *(const float4*)(p);
        rb1 = *(const float4*)(p + 4);
        rc0 = *(const float4*)(p + 64);
        rc1 = *(const float4*)(p + 68);
    };
    auto stsB = [&](int buf, uint32_t halfoff) {
        uint4 v0, v1;
        v0.x = h2bits(__floats2half2_rn(rb0.x, rb0.y));
        v0.y = h2bits(__floats2half2_rn(rb0.z, rb0.w));
        v0.z = h2bits(__floats2half2_rn(rb1.x, rb1.y));
        v0.w = h2bits(__floats2half2_rn(rb1.z, rb1.w));
        v1.x = h2bits(__floats2half2_rn(rc0.x, rc0.y));
        v1.y = h2bits(__floats2half2_rn(rc0.z, rc0.w));
        v1.z = h2bits(__floats2half2_rn(rc1.x, rc1.y));
        v1.w = h2bits(__floats2half2_rn(rc1.z, rc1.w));
        char* bb = sm + buf * STAGE + A_TILE + halfoff;
        *(uint4*)(bb + b_q0) = v0;
        *(uint4*)(bb + b_q1) = v1;
    };

    auto compute4 = [&](int buf, int ksbase) {
        const uint32_t Ab = warpA + buf * STAGE;
        const uint32_t Bb = sb + buf * STAGE + A_TILE;
        #pragma unroll
        for (int ki = 0; ki < 4; ++ki) {
            const int ks = ksbase + ki;
            uint32_t af[4][4];
            #pragma unroll
            for (int mt = 0; mt < 4; ++mt)
                ldsm4(af[mt], Ab + mt * 4096 +
                      (uint32_t)(((ks * 2 + lhi) ^ lr7) << 4));
            uint32_t bf[2][4];
            const uint32_t Bk = Bb + ks * 4096;
            ldsm4t(bf[0], Bk + boff[0]);
            ldsm4t(bf[1], Bk + boff[1]);
            #pragma unroll
            for (int mt = 0; mt < 4; ++mt)
                #pragma unroll
                for (int nt = 0; nt < 4; ++nt)
                    mma_f16(acc[mt][nt], af[mt],
                            bf[nt >> 1][(nt & 1) * 2], bf[nt >> 1][(nt & 1) * 2 + 1]);
        }
    };

    const int S = K / BK;                 // 8 (layer1) or 32 (layer2)

    // Preamble: A stage0 async; B stage0 both halves direct; h0 of stage1 in regs.
    cpA(0, 0); CP_COMMIT();
    ldgB(w0);                 stsB(0, 0);
    ldgB(w0 + w_half);        stsB(0, BHALF);
    ldgB(w0 + w_stage);       // stage-1 h0
    CP_WAIT0();
    __syncthreads();

    #pragma unroll 1
    for (int s = 0; s < S; ++s) {
        const int buf = s & 1, nbuf = buf ^ 1;

        if (s + 1 < S) {
            cpA(s + 1, nbuf); CP_COMMIT();
            stsB(nbuf, 0);                                  // h0(s+1), regs from prev iter
            ldgB(w0 + (size_t)(s + 1) * w_stage + w_half);  // h1(s+1)
        }
        compute4(buf, 0);
        if (s + 1 < S) {
            stsB(nbuf, BHALF);                              // h1(s+1)
            if (s + 2 < S)
                ldgB(w0 + (size_t)(s + 2) * w_stage);       // h0(s+2)
        }
        compute4(buf, 4);
        if (s + 1 < S) CP_WAIT0();
        __syncthreads();
    }

    // Epilogue: +bias (fp32), optional relu; store fp16 (h) or fp32 (out).
    #pragma unroll
    for (int mt = 0; mt < 4; ++mt) {
        const int r = m0 + wm * 64 + mt * 16 + g;
        #pragma unroll
        for (int nt = 0; nt < 4; ++nt) {
            const int c = n0 + wn * 32 + nt * 8 + tg * 2;
            const float b0v = bias[c], b1v = bias[c + 1];
            float v0 = acc[mt][nt][0] + b0v;
            float v1 = acc[mt][nt][1] + b1v;
            float v2 = acc[mt][nt][2] + b0v;
            float v3 = acc[mt][nt][3] + b1v;
            if (RELU) {
                v0 = fmaxf(v0, 0.f); v1 = fmaxf(v1, 0.f);
                v2 = fmaxf(v2, 0.f); v3 = fmaxf(v3, 0.f);
            }
            if (OUT_HALF) {
                __half* C = (__half*)Cg + (size_t)blockIdx.z * cBatch;
                *(__half2*)(C + (size_t)r * ldc + c)       = __floats2half2_rn(v0, v1);
                *(__half2*)(C + (size_t)(r + 8) * ldc + c) = __floats2half2_rn(v2, v3);
            } else {
                float* C = (float*)Cg + (size_t)blockIdx.z * cBatch;
                float2 p0; p0.x = v0; p0.y = v1;
                float2 p1; p1.x = v2; p1.y = v3;
                *(float2*)(C + (size_t)r * ldc + c)       = p0;
                *(float2*)(C + (size_t)(r + 8) * ldc + c) = p1;
            }
        }
    }
}

} // anonymous namespace

extern "C" void kernel_launch(void* const* d_in, const int* in_sizes, int n_in,
                              void* d_out, int out_size) {
    (void)in_sizes; (void)n_in; (void)out_size;
    const float* x  = (const float*)d_in[0];  // [B, M, DIN]
    const float* W1 = (const float*)d_in[1];  // [M, DIN, DH]
    const float* b1 = (const float*)d_in[2];  // [M, DH]
    const float* W2 = (const float*)d_in[3];  // [M, DH, DOUT]
    const float* b2 = (const float*)d_in[4];  // [M, DOUT]
    float* out = (float*)d_out;               // [B, M, DOUT]

    __half* h = nullptr;
    cudaGetSymbolAddress((void**)&h, g_h);
    __half* x_h = nullptr;
    cudaGetSymbolAddress((void**)&x_h, g_x_h);

    cudaFuncSetAttribute(gemm_f16<true, true>,   cudaFuncAttributeMaxDynamicSharedMemorySize, SMEM_DYN);
    cudaFuncSetAttribute(gemm_f16<false, false>, cudaFuncAttributeMaxDynamicSharedMemorySize, SMEM_DYN);

    // Pre-pass: x -> fp16 (~17 us)
    {
        const int n4 = Bsz * Msl * DIN / 4;
        cvt_f16<<<(n4 + 255) / 256, 256>>>((const float4*)x, (uint2*)x_h, n4);
    }

    dim3 blk(TPB);

    // Layer 1: per m, h[b, n] = fp16(relu(x[b,:] @ W1 + b1))
    dim3 g1(DH / BN, Bsz / BM, Msl);
    gemm_f16<true, true><<<g1, blk, SMEM_DYN>>>(
        x_h, W1, b1, h, DIN,
        /*aBatch*/ (long)DIN,        /*lda*/ Msl * DIN,
        /*wBatch*/ (long)DIN * DH,   /*ldw*/ DH,
        /*biasBatch*/ (long)DH,
        /*cBatch*/ (long)Bsz * DH,   /*ldc*/ DH);

    // Layer 2: per m, out[b, n] = h[b,:] @ W2 + b2 (fp32 out)
    dim3 g2(DOUT / BN, Bsz / BM, Msl);
    gemm_f16<false, false><<<g2, blk, SMEM_DYN>>>(
        h, W2, b2, out, DH,
        /*aBatch*/ (long)Bsz * DH,   /*lda*/ DH,
        /*wBatch*/ (long)DH * DOUT,  /*ldw*/ DOUT,
        /*biasBatch*/ (long)DOUT,
        /*cBatch*/ (long)DOUT,       /*ldc*/ Msl * DOUT);
}